// round 10
// baseline (speedup 1.0000x reference)
#include <cuda_runtime.h>
#include <cstdint>
#include <cfloat>

#define DL 21
#define SS 512
#define HW (SS*SS)
#define NB 4
#define NE (NB*DL*HW)   // 22,020,096 (~84 MB fp32)
#define TC 16           // columns per sweep block

// Spatially transposed unary (b,l,x,y) and edge weights for dirs 0/1
__device__ __align__(16) float g_uT[NE];
__device__ __align__(16) float g_ewT[NB*2*HW];
// Directional results: o0/o1 in transposed space; o2 carries -3u
__device__ __align__(16) float g_o0[NE];
__device__ __align__(16) float g_o1[NE];
__device__ __align__(16) float g_o2[NE];
__device__ __align__(16) float g_o3[NE];

// ---------------------------------------------------------------------------
// Packed f32x2 helpers (fma only — packed min does not exist on sm_10x)
typedef unsigned long long u64;
__device__ __forceinline__ u64 f2u(float x, float y) {
    u64 r; asm("mov.b64 %0, {%1, %2};" : "=l"(r) : "f"(x), "f"(y)); return r;
}
__device__ __forceinline__ float2 u2f(u64 v) {
    float2 r; asm("mov.b64 {%0, %1}, %2;" : "=f"(r.x), "=f"(r.y) : "l"(v)); return r;
}
__device__ __forceinline__ u64 ffma2u(u64 a, u64 b, u64 c) {
    u64 d; asm("fma.rn.f32x2 %0, %1, %2, %3;" : "=l"(d) : "l"(a), "l"(b), "l"(c)); return d;
}

// ---------------------------------------------------------------------------
// 32x32 tile transpose using float4, conflict-free padded tile
__device__ __forceinline__ void tr_tile4(const float* __restrict__ sp,
                                         float* __restrict__ dp, int tt, int tid) {
    __shared__ float tile[32][33];
    const int ty0 = (tt >> 4) << 5;
    const int tx0 = (tt & 15) << 5;
    const int r  = tid >> 3;
    const int q4 = (tid & 7) << 2;
    float4 v = *reinterpret_cast<const float4*>(sp + (size_t)(ty0 + r) * SS + tx0 + q4);
    tile[r][q4 + 0] = v.x; tile[r][q4 + 1] = v.y;
    tile[r][q4 + 2] = v.z; tile[r][q4 + 3] = v.w;
    __syncthreads();
    float4 o = make_float4(tile[q4 + 0][r], tile[q4 + 1][r],
                           tile[q4 + 2][r], tile[q4 + 3][r]);
    *reinterpret_cast<float4*>(dp + (size_t)(tx0 + r) * SS + ty0 + q4) = o;
}

// planes 0..83: unary; 84..91: edge weights dirs 0/1
__global__ void __launch_bounds__(256)
transpose_all(const float* __restrict__ u, const float* __restrict__ ew) {
    const int plane = blockIdx.x >> 8;
    const int tt = blockIdx.x & 255;
    if (plane < NB * DL) {
        tr_tile4(u + (size_t)plane * HW, g_uT + (size_t)plane * HW, tt, threadIdx.x);
    } else {
        const int p = plane - NB * DL;          // 0..7
        const int b = p >> 1, d = p & 1;
        tr_tile4(ew + (size_t)(b * 4 + d) * HW, g_ewT + (size_t)p * HW, tt, threadIdx.x);
    }
}

// ---------------------------------------------------------------------------
// Sweep: block = 16 columns x 11 label-pair groups (176 threads), smem
// L-exchange [wp][kk][c] (conflict-free), depth-2 prefetch, FFMA2 math.
// 512 blocks -> ~3.5 barrier groups per SM for latency overlap.
template<int DIR>
__device__ __forceinline__ void run_sweep(const float* __restrict__ u,
                                          const float* __restrict__ ew,
                                          int b, int col0, int c, int lg,
                                          bool has2, int base0, int base1,
                                          const u64 (&Vp0)[11],
                                          const u64 (&Vp1)[11],
                                          u64 (*Lb)[11][TC]) {
    const float* src  = (DIR < 2) ? g_uT : u;
    const float* wsrc = (DIR < 2) ? (g_ewT + (size_t)(b * 2 + DIR) * HW)
                                  : (ew   + (size_t)(b * 4 + DIR) * HW);
    float* dst = (DIR == 0) ? g_o0 : (DIR == 1) ? g_o1 : (DIR == 2) ? g_o2 : g_o3;
    constexpr int STRD = (DIR == 0 || DIR == 2) ? SS : -SS;
    const int start = (STRD > 0) ? 0 : (SS - 1) * SS;
    const int wb = col0 + c;

    float L0, L1;
    int offL = start;
    // t = 0 (border: L = u)
    {
        float cu0 = __ldg(src + base0 + offL);
        float cu1 = __ldg(src + base1 + offL);
        L0 = cu0; L1 = cu1;
        dst[base0 + offL] = (DIR == 2) ? fmaf(-3.0f, cu0, L0) : L0;
        if (has2) dst[base1 + offL] = (DIR == 2) ? fmaf(-3.0f, cu1, L1) : L1;
        Lb[0][lg][c] = f2u(L0, has2 ? L1 : FLT_MAX);
    }
    // prefetch t = 1, t = 2
    offL += STRD;
    float au0 = __ldg(src + base0 + offL);
    float au1 = __ldg(src + base1 + offL);
    float aw  = __ldg(wsrc + wb + offL);
    offL += STRD;
    float bu0 = __ldg(src + base0 + offL);
    float bu1 = __ldg(src + base1 + offL);
    float bw  = __ldg(wsrc + wb + offL);
    __syncthreads();

    auto stepf = [&](int wp, float u0v, float u1v, float wv, int offS) {
        const u64 (*Lo)[TC] = Lb[wp ^ 1];
        const u64 w2 = f2u(wv, wv);
        u64 xu = Lo[0][c];
        float2 cA = u2f(ffma2u(w2, Vp0[0], xu));
        float2 cE = u2f(ffma2u(w2, Vp1[0], xu));
        float a0 = cA.x, a1 = cA.y, e0 = cE.x, e1 = cE.y;
#pragma unroll
        for (int kk = 1; kk < 11; kk++) {
            xu = Lo[kk][c];
            cA = u2f(ffma2u(w2, Vp0[kk], xu));
            cE = u2f(ffma2u(w2, Vp1[kk], xu));
            a0 = fminf(a0, cA.x); a1 = fminf(a1, cA.y);
            e0 = fminf(e0, cE.x); e1 = fminf(e1, cE.y);
        }
        L0 = u0v + fminf(a0, a1);
        L1 = u1v + fminf(e0, e1);
        dst[base0 + offS] = (DIR == 2) ? fmaf(-3.0f, u0v, L0) : L0;
        if (has2) dst[base1 + offS] = (DIR == 2) ? fmaf(-3.0f, u1v, L1) : L1;
        Lb[wp][lg][c] = f2u(L0, has2 ? L1 : FLT_MAX);
    };

    int offS = start;
#pragma unroll 1
    for (int t = 1; t <= SS - 3; t++) {
        offS += STRD;
        stepf(t & 1, au0, au1, aw, offS);
        au0 = bu0; au1 = bu1; aw = bw;
        offL += STRD;
        bu0 = __ldg(src + base0 + offL);
        bu1 = __ldg(src + base1 + offL);
        bw  = __ldg(wsrc + wb + offL);
        __syncthreads();
    }
    // t = SS-2
    offS += STRD;
    stepf((SS - 2) & 1, au0, au1, aw, offS);
    au0 = bu0; au1 = bu1; aw = bw;
    __syncthreads();
    // t = SS-1
    offS += STRD;
    stepf((SS - 1) & 1, au0, au1, aw, offS);
}

__global__ void __launch_bounds__(176, 5)
sweep(const float* __restrict__ u, const float* __restrict__ ew,
      const float* __restrict__ lc) {
    __shared__ u64 Lb[2][11][TC];
    const int bx   = blockIdx.x;              // 512 blocks
    const int dir  = bx >> 7;
    const int b    = (bx >> 5) & 3;
    const int col0 = (bx & 31) << 4;          // 32 col-groups x 16 cols
    const int c    = threadIdx.x & 15;
    const int lg   = threadIdx.x >> 4;        // 0..10
    const int l0   = 2 * lg;
    const bool has2 = (lg < 10);
    const int l1   = has2 ? l0 + 1 : l0;

    // V pairs packed along k (source label): Vp[kk] = {V[2kk][l], V[2kk+1][l]}
    u64 Vp0[11], Vp1[11];
#pragma unroll
    for (int kk = 0; kk < 11; kk++) {
        const int ka = 2 * kk, kb = 2 * kk + 1;
        float va0 = __ldg(lc + ka * DL + l0);
        float vb0 = (kb < DL) ? __ldg(lc + kb * DL + l0) : 0.0f;
        float va1 = __ldg(lc + ka * DL + l1);
        float vb1 = (kb < DL) ? __ldg(lc + kb * DL + l1) : 0.0f;
        Vp0[kk] = f2u(va0, vb0);
        Vp1[kk] = f2u(va1, vb1);
    }

    const int base0 = (b * DL + l0) * HW + col0 + c;
    const int base1 = (b * DL + l1) * HW + col0 + c;

    if (dir == 0)      run_sweep<0>(u, ew, b, col0, c, lg, has2, base0, base1, Vp0, Vp1, Lb);
    else if (dir == 1) run_sweep<1>(u, ew, b, col0, c, lg, has2, base0, base1, Vp0, Vp1, Lb);
    else if (dir == 2) run_sweep<2>(u, ew, b, col0, c, lg, has2, base0, base1, Vp0, Vp1, Lb);
    else               run_sweep<3>(u, ew, b, col0, c, lg, has2, base0, base1, Vp0, Vp1, Lb);
}

// ---------------------------------------------------------------------------
// out(b,l,y,x) = o2(y,x) + o3(y,x) + o0(x,y) + o1(x,y)   [o2 carries -3u]
__global__ void __launch_bounds__(256)
combine(float* __restrict__ out) {
    __shared__ float t0[32][33], t1[32][33];
    const int plane = blockIdx.x >> 8;       // b*21+l
    const int tt = blockIdx.x & 255;
    const int y0 = (tt >> 4) << 5;
    const int x0 = (tt & 15) << 5;
    const size_t pb = (size_t)plane * HW;
    const int r  = threadIdx.x >> 3;
    const int q4 = (threadIdx.x & 7) << 2;
    {   // load transposed planes: rows along x, vectorized along y
        size_t idx = pb + (size_t)(x0 + r) * SS + y0 + q4;
        float4 a = *reinterpret_cast<const float4*>(g_o0 + idx);
        float4 bq = *reinterpret_cast<const float4*>(g_o1 + idx);
        t0[r][q4 + 0] = a.x;  t0[r][q4 + 1] = a.y;
        t0[r][q4 + 2] = a.z;  t0[r][q4 + 3] = a.w;
        t1[r][q4 + 0] = bq.x; t1[r][q4 + 1] = bq.y;
        t1[r][q4 + 2] = bq.z; t1[r][q4 + 3] = bq.w;
    }
    __syncthreads();
    {   // stream o2/o3 + add transposed tiles, vectorized along x
        size_t idx = pb + (size_t)(y0 + r) * SS + x0 + q4;
        float4 r2 = *reinterpret_cast<const float4*>(g_o2 + idx);
        float4 r3 = *reinterpret_cast<const float4*>(g_o3 + idx);
        float4 o;
        o.x = r2.x + r3.x + t0[q4 + 0][r] + t1[q4 + 0][r];
        o.y = r2.y + r3.y + t0[q4 + 1][r] + t1[q4 + 1][r];
        o.z = r2.z + r3.z + t0[q4 + 2][r] + t1[q4 + 2][r];
        o.w = r2.w + r3.w + t0[q4 + 3][r] + t1[q4 + 3][r];
        *reinterpret_cast<float4*>(out + idx) = o;
    }
}

// ---------------------------------------------------------------------------
extern "C" void kernel_launch(void* const* d_in, const int* in_sizes, int n_in,
                              void* d_out, int out_size) {
    const float* unary = (const float*)d_in[0];   // (4,1,21,512,512)
    const float* ew    = (const float*)d_in[1];   // (4,4,512,512)
    const float* lc    = (const float*)d_in[2];   // (21,21)
    float* out = (float*)d_out;                   // (4,1,21,512,512)

    transpose_all<<<(NB * DL + NB * 2) * 256, 256>>>(unary, ew);
    sweep<<<512, 176>>>(unary, ew, lc);
    combine<<<NB * DL * 256, 256>>>(out);
}

// round 11
// speedup vs baseline: 1.8148x; 1.8148x over previous
#include <cuda_runtime.h>
#include <cstdint>
#include <cfloat>

#define DL 21
#define SS 512
#define HW (SS*SS)
#define NB 4
#define NE (NB*DL*HW)   // 22,020,096 (~84 MB fp32)
#define TC 64           // columns per sweep block

// Spatially transposed unary (b,l,x,y) and edge weights for dirs 0/1
__device__ __align__(16) float g_uT[NE];
__device__ __align__(16) float g_ewT[NB*2*HW];
// Directional results: o0/o1 in transposed space; o2 carries -3u
__device__ __align__(16) float g_o0[NE];
__device__ __align__(16) float g_o1[NE];
__device__ __align__(16) float g_o2[NE];
__device__ __align__(16) float g_o3[NE];

// ---------------------------------------------------------------------------
// Packed f32x2 helpers (fma only — packed min does not exist on sm_10x)
typedef unsigned long long u64;
__device__ __forceinline__ u64 f2u(float x, float y) {
    u64 r; asm("mov.b64 %0, {%1, %2};" : "=l"(r) : "f"(x), "f"(y)); return r;
}
__device__ __forceinline__ float2 u2f(u64 v) {
    float2 r; asm("mov.b64 {%0, %1}, %2;" : "=f"(r.x), "=f"(r.y) : "l"(v)); return r;
}
__device__ __forceinline__ u64 ffma2u(u64 a, u64 b, u64 c) {
    u64 d; asm("fma.rn.f32x2 %0, %1, %2, %3;" : "=l"(d) : "l"(a), "l"(b), "l"(c)); return d;
}

// ---------------------------------------------------------------------------
// 32x32 tile transpose using float4, conflict-free padded tile
__device__ __forceinline__ void tr_tile4(const float* __restrict__ sp,
                                         float* __restrict__ dp, int tt, int tid) {
    __shared__ float tile[32][33];
    const int ty0 = (tt >> 4) << 5;
    const int tx0 = (tt & 15) << 5;
    const int r  = tid >> 3;
    const int q4 = (tid & 7) << 2;
    float4 v = *reinterpret_cast<const float4*>(sp + (size_t)(ty0 + r) * SS + tx0 + q4);
    tile[r][q4 + 0] = v.x; tile[r][q4 + 1] = v.y;
    tile[r][q4 + 2] = v.z; tile[r][q4 + 3] = v.w;
    __syncthreads();
    float4 o = make_float4(tile[q4 + 0][r], tile[q4 + 1][r],
                           tile[q4 + 2][r], tile[q4 + 3][r]);
    *reinterpret_cast<float4*>(dp + (size_t)(tx0 + r) * SS + ty0 + q4) = o;
}

// planes 0..83: unary; 84..91: edge weights dirs 0/1
__global__ void __launch_bounds__(256)
transpose_all(const float* __restrict__ u, const float* __restrict__ ew) {
    const int plane = blockIdx.x >> 8;
    const int tt = blockIdx.x & 255;
    if (plane < NB * DL) {
        tr_tile4(u + (size_t)plane * HW, g_uT + (size_t)plane * HW, tt, threadIdx.x);
    } else {
        const int p = plane - NB * DL;          // 0..7
        const int b = p >> 1, d = p & 1;
        tr_tile4(ew + (size_t)(b * 4 + d) * HW, g_ewT + (size_t)p * HW, tt, threadIdx.x);
    }
}

// ---------------------------------------------------------------------------
// Sweep: block = 64 columns x 11 label-pair groups (704 threads), one block
// per SM, 128 blocks total -> HALF the block-steps of the 32-col version.
// Lb layout [wp][kk][c] (c innermost, conflict-free), depth-2 prefetch,
// FFMA2-packed inner loop.
template<int DIR>
__device__ __forceinline__ void run_sweep(const float* __restrict__ u,
                                          const float* __restrict__ ew,
                                          int b, int col0, int c, int lg,
                                          bool has2, int base0, int base1,
                                          const u64 (&Vp0)[11],
                                          const u64 (&Vp1)[11],
                                          u64 (*Lb)[11][TC]) {
    const float* src  = (DIR < 2) ? g_uT : u;
    const float* wsrc = (DIR < 2) ? (g_ewT + (size_t)(b * 2 + DIR) * HW)
                                  : (ew   + (size_t)(b * 4 + DIR) * HW);
    float* dst = (DIR == 0) ? g_o0 : (DIR == 1) ? g_o1 : (DIR == 2) ? g_o2 : g_o3;
    constexpr int STRD = (DIR == 0 || DIR == 2) ? SS : -SS;
    const int start = (STRD > 0) ? 0 : (SS - 1) * SS;
    const int wb = col0 + c;

    float L0, L1;
    int offL = start;
    // t = 0 (border: L = u)
    {
        float cu0 = __ldg(src + base0 + offL);
        float cu1 = __ldg(src + base1 + offL);
        L0 = cu0; L1 = cu1;
        dst[base0 + offL] = (DIR == 2) ? fmaf(-3.0f, cu0, L0) : L0;
        if (has2) dst[base1 + offL] = (DIR == 2) ? fmaf(-3.0f, cu1, L1) : L1;
        Lb[0][lg][c] = f2u(L0, has2 ? L1 : FLT_MAX);
    }
    // prefetch t = 1, t = 2
    offL += STRD;
    float au0 = __ldg(src + base0 + offL);
    float au1 = __ldg(src + base1 + offL);
    float aw  = __ldg(wsrc + wb + offL);
    offL += STRD;
    float bu0 = __ldg(src + base0 + offL);
    float bu1 = __ldg(src + base1 + offL);
    float bw  = __ldg(wsrc + wb + offL);
    __syncthreads();

    auto stepf = [&](int wp, float u0v, float u1v, float wv, int offS) {
        const u64 (*Lo)[TC] = Lb[wp ^ 1];
        const u64 w2 = f2u(wv, wv);
        u64 xu = Lo[0][c];
        float2 cA = u2f(ffma2u(w2, Vp0[0], xu));
        float2 cE = u2f(ffma2u(w2, Vp1[0], xu));
        float a0 = cA.x, a1 = cA.y, e0 = cE.x, e1 = cE.y;
#pragma unroll
        for (int kk = 1; kk < 11; kk++) {
            xu = Lo[kk][c];
            cA = u2f(ffma2u(w2, Vp0[kk], xu));
            cE = u2f(ffma2u(w2, Vp1[kk], xu));
            a0 = fminf(a0, cA.x); a1 = fminf(a1, cA.y);
            e0 = fminf(e0, cE.x); e1 = fminf(e1, cE.y);
        }
        L0 = u0v + fminf(a0, a1);
        L1 = u1v + fminf(e0, e1);
        dst[base0 + offS] = (DIR == 2) ? fmaf(-3.0f, u0v, L0) : L0;
        if (has2) dst[base1 + offS] = (DIR == 2) ? fmaf(-3.0f, u1v, L1) : L1;
        Lb[wp][lg][c] = f2u(L0, has2 ? L1 : FLT_MAX);
    };

    int offS = start;
#pragma unroll 1
    for (int t = 1; t <= SS - 3; t++) {
        offS += STRD;
        stepf(t & 1, au0, au1, aw, offS);
        au0 = bu0; au1 = bu1; aw = bw;
        offL += STRD;
        bu0 = __ldg(src + base0 + offL);
        bu1 = __ldg(src + base1 + offL);
        bw  = __ldg(wsrc + wb + offL);
        __syncthreads();
    }
    // t = SS-2
    offS += STRD;
    stepf((SS - 2) & 1, au0, au1, aw, offS);
    au0 = bu0; au1 = bu1; aw = bw;
    __syncthreads();
    // t = SS-1
    offS += STRD;
    stepf((SS - 1) & 1, au0, au1, aw, offS);
}

__global__ void __launch_bounds__(704, 1)
sweep(const float* __restrict__ u, const float* __restrict__ ew,
      const float* __restrict__ lc) {
    __shared__ u64 Lb[2][11][TC];
    const int bx   = blockIdx.x;              // 128 blocks
    const int dir  = bx >> 5;
    const int b    = (bx >> 3) & 3;
    const int col0 = (bx & 7) << 6;           // 8 col-groups x 64 cols
    const int c    = threadIdx.x & 63;
    const int lg   = threadIdx.x >> 6;        // 0..10
    const int l0   = 2 * lg;
    const bool has2 = (lg < 10);
    const int l1   = has2 ? l0 + 1 : l0;

    // V pairs packed along k (source label): Vp[kk] = {V[2kk][l], V[2kk+1][l]}
    u64 Vp0[11], Vp1[11];
#pragma unroll
    for (int kk = 0; kk < 11; kk++) {
        const int ka = 2 * kk, kb = 2 * kk + 1;
        float va0 = __ldg(lc + ka * DL + l0);
        float vb0 = (kb < DL) ? __ldg(lc + kb * DL + l0) : 0.0f;
        float va1 = __ldg(lc + ka * DL + l1);
        float vb1 = (kb < DL) ? __ldg(lc + kb * DL + l1) : 0.0f;
        Vp0[kk] = f2u(va0, vb0);
        Vp1[kk] = f2u(va1, vb1);
    }

    const int base0 = (b * DL + l0) * HW + col0 + c;
    const int base1 = (b * DL + l1) * HW + col0 + c;

    if (dir == 0)      run_sweep<0>(u, ew, b, col0, c, lg, has2, base0, base1, Vp0, Vp1, Lb);
    else if (dir == 1) run_sweep<1>(u, ew, b, col0, c, lg, has2, base0, base1, Vp0, Vp1, Lb);
    else if (dir == 2) run_sweep<2>(u, ew, b, col0, c, lg, has2, base0, base1, Vp0, Vp1, Lb);
    else               run_sweep<3>(u, ew, b, col0, c, lg, has2, base0, base1, Vp0, Vp1, Lb);
}

// ---------------------------------------------------------------------------
// out(b,l,y,x) = o2(y,x) + o3(y,x) + o0(x,y) + o1(x,y)   [o2 carries -3u]
__global__ void __launch_bounds__(256)
combine(float* __restrict__ out) {
    __shared__ float t0[32][33], t1[32][33];
    const int plane = blockIdx.x >> 8;       // b*21+l
    const int tt = blockIdx.x & 255;
    const int y0 = (tt >> 4) << 5;
    const int x0 = (tt & 15) << 5;
    const size_t pb = (size_t)plane * HW;
    const int r  = threadIdx.x >> 3;
    const int q4 = (threadIdx.x & 7) << 2;
    {   // load transposed planes: rows along x, vectorized along y
        size_t idx = pb + (size_t)(x0 + r) * SS + y0 + q4;
        float4 a = *reinterpret_cast<const float4*>(g_o0 + idx);
        float4 bq = *reinterpret_cast<const float4*>(g_o1 + idx);
        t0[r][q4 + 0] = a.x;  t0[r][q4 + 1] = a.y;
        t0[r][q4 + 2] = a.z;  t0[r][q4 + 3] = a.w;
        t1[r][q4 + 0] = bq.x; t1[r][q4 + 1] = bq.y;
        t1[r][q4 + 2] = bq.z; t1[r][q4 + 3] = bq.w;
    }
    __syncthreads();
    {   // stream o2/o3 + add transposed tiles, vectorized along x
        size_t idx = pb + (size_t)(y0 + r) * SS + x0 + q4;
        float4 r2 = *reinterpret_cast<const float4*>(g_o2 + idx);
        float4 r3 = *reinterpret_cast<const float4*>(g_o3 + idx);
        float4 o;
        o.x = r2.x + r3.x + t0[q4 + 0][r] + t1[q4 + 0][r];
        o.y = r2.y + r3.y + t0[q4 + 1][r] + t1[q4 + 1][r];
        o.z = r2.z + r3.z + t0[q4 + 2][r] + t1[q4 + 2][r];
        o.w = r2.w + r3.w + t0[q4 + 3][r] + t1[q4 + 3][r];
        *reinterpret_cast<float4*>(out + idx) = o;
    }
}

// ---------------------------------------------------------------------------
extern "C" void kernel_launch(void* const* d_in, const int* in_sizes, int n_in,
                              void* d_out, int out_size) {
    const float* unary = (const float*)d_in[0];   // (4,1,21,512,512)
    const float* ew    = (const float*)d_in[1];   // (4,4,512,512)
    const float* lc    = (const float*)d_in[2];   // (21,21)
    float* out = (float*)d_out;                   // (4,1,21,512,512)

    transpose_all<<<(NB * DL + NB * 2) * 256, 256>>>(unary, ew);
    sweep<<<128, 704>>>(unary, ew, lc);
    combine<<<NB * DL * 256, 256>>>(out);
}